// round 14
// baseline (speedup 1.0000x reference)
#include <cuda_runtime.h>
#include <cstdint>

// ---------------------------------------------------------------------------
// out[m] = sum_n I_n * exp(-0.5 (x-mu)^T A (x-mu))
//        = sum_n exp2( monomials(x_m) . coef_n )       (everything folded)
// coef order k=0..7 : x2,y2,z2,xy | xz,yz,x,y   -> handled by mma.sync tf32
// k=8 (z), k=9 (1=cf) -> scalar f32 tail folded into the MMA C operand.
//
// R14: hybrid exp2 — MUFU ex2 for 6.5/8 values, FMA-pipe Taylor-5 exp2 for
//      1.5/8 (static lane assignment, unroll-2 parity). Balances MUFU (was
//      72% busy, top pipe) against FMA (~22%): both land ~58%.
//      Core layout/scheduling identical to R13.
// ---------------------------------------------------------------------------

#define NG_MAX 8192
#define CHUNK_FLOATS 144   // per 8-gaussian chunk: 8*16 mma floats + 16 scalar
#define SPLIT_G 256
#define NCHUNK 32          // chunks per split
#define SPLIT_FLOATS (NCHUNK * CHUNK_FLOATS)   // 4608 floats = 18432 B
#define PTB 256            // points per CTA ticket
#define CTAS_PER_SM 3

__device__ __align__(16) float g_b[(NG_MAX / 8) * CHUNK_FLOATS];

// ---- helpers ---------------------------------------------------------------
__device__ __forceinline__ float ex2(float x) {
    float y;
    asm("ex2.approx.ftz.f32 %0, %1;" : "=f"(y) : "f"(x));
    return y;
}
// FMA-pipe exp2 for t <= 0 (clamped at -125). Taylor-5 on [-0.5, 0.5].
__device__ __forceinline__ float exp2poly(float t) {
    float tc = fmaxf(t, -125.0f);
    float r  = tc + 12582912.0f;                    // 2^23+2^22: RN to int
    int   k  = __float_as_int(r) - 0x4B400000;      // integer part
    float f  = tc - (r - 12582912.0f);              // frac in [-0.5, 0.5]
    float p  = 0.001333355815f;
    p = fmaf(p, f, 0.009618129107f);
    p = fmaf(p, f, 0.055504108664f);
    p = fmaf(p, f, 0.240226506959f);
    p = fmaf(p, f, 0.693147180560f);
    p = fmaf(p, f, 1.0f);
    float s = __int_as_float((k + 127) << 23);      // 2^k (k in [-125, 0])
    return p * s;
}
__device__ __forceinline__ uint32_t tf32_of(float v) {
    uint32_t r;
    asm("cvt.rna.tf32.f32 %0, %1;" : "=r"(r) : "f"(v));
    return r;
}
__device__ __forceinline__ void tf32split(float v, uint32_t& hi, uint32_t& lo) {
    hi = tf32_of(v);
    lo = tf32_of(v - __uint_as_float(hi));
}
__device__ __forceinline__ uint32_t smem_u32(const void* p) {
    uint32_t a;
    asm("{ .reg .u64 t; cvta.to.shared.u64 t, %1; cvt.u32.u64 %0, t; }"
        : "=r"(a) : "l"(p));
    return a;
}
__device__ __forceinline__ void cp_async16(uint32_t dst, const void* src) {
    asm volatile("cp.async.cg.shared.global [%0], [%1], 16;"
                 :: "r"(dst), "l"(src));
}
__device__ __forceinline__ void cp_commit() {
    asm volatile("cp.async.commit_group;");
}
__device__ __forceinline__ void cp_wait0() {
    asm volatile("cp.async.wait_group 0;");
}

// D = A(tf32) * B(tf32) + C   (m16n8k8, row.col)
__device__ __forceinline__ void mma8(float d[4], const uint32_t a[4],
                                     uint32_t b0, uint32_t b1,
                                     float c0, float c1, float c2, float c3) {
    asm("mma.sync.aligned.m16n8k8.row.col.f32.tf32.tf32.f32 "
        "{%0,%1,%2,%3}, {%4,%5,%6,%7}, {%8,%9}, {%10,%11,%12,%13};"
        : "=f"(d[0]), "=f"(d[1]), "=f"(d[2]), "=f"(d[3])
        : "r"(a[0]), "r"(a[1]), "r"(a[2]), "r"(a[3]),
          "r"(b0), "r"(b1),
          "f"(c0), "f"(c1), "f"(c2), "f"(c3));
}

// ---------------------------------------------------------------------------
// Prep: 10 coefficients per gaussian, packed for per-lane fragment loads.
// chunk c = g/8, slot i = g%8, chunk base = c*144 floats:
//   mma region  [(i*4 + j)*4 .. +4) = (hi[v_j], hi[v_{j+4}], lo[v_j], lo[v_{j+4}])
//   scalar      [128 + i*2]         = (v8 (z coef), v9 (cf))
// ---------------------------------------------------------------------------
__global__ void prep_kernel(const float* __restrict__ positions,
                            const float* __restrict__ scales,
                            const float* __restrict__ rotations,
                            const float* __restrict__ intensities,
                            int n, int n_pad) {
    int g = blockIdx.x * blockDim.x + threadIdx.x;
    if (g >= n_pad || g >= NG_MAX) return;

    float v[10];
    if (g >= n) {
#pragma unroll
        for (int k = 0; k < 9; k++) v[k] = 0.0f;
        v[9] = -1000.0f;  // exp2 -> 0
    } else {
        float qw = rotations[4 * g + 0];
        float qx = rotations[4 * g + 1];
        float qy = rotations[4 * g + 2];
        float qz = rotations[4 * g + 3];
        float nrm = sqrtf(qw * qw + qx * qx + qy * qy + qz * qz);
        float inv = 1.0f / (nrm + 1e-8f);
        qw *= inv; qx *= inv; qy *= inv; qz *= inv;

        float r00 = 1.0f - 2.0f * (qy * qy + qz * qz);
        float r01 = 2.0f * (qx * qy - qz * qw);
        float r02 = 2.0f * (qx * qz + qy * qw);
        float r10 = 2.0f * (qx * qy + qz * qw);
        float r11 = 1.0f - 2.0f * (qx * qx + qz * qz);
        float r12 = 2.0f * (qy * qz - qx * qw);
        float r20 = 2.0f * (qx * qz - qy * qw);
        float r21 = 2.0f * (qy * qz + qx * qw);
        float r22 = 1.0f - 2.0f * (qx * qx + qy * qy);

        float s0 = fabsf(scales[3 * g + 0]) + 1e-6f;
        float s1 = fabsf(scales[3 * g + 1]) + 1e-6f;
        float s2 = fabsf(scales[3 * g + 2]) + 1e-6f;
        float i0 = 1.0f / (s0 * s0);
        float i1 = 1.0f / (s1 * s1);
        float i2 = 1.0f / (s2 * s2);

        float a00 = r00 * r00 * i0 + r01 * r01 * i1 + r02 * r02 * i2;
        float a01 = r00 * r10 * i0 + r01 * r11 * i1 + r02 * r12 * i2;
        float a02 = r00 * r20 * i0 + r01 * r21 * i1 + r02 * r22 * i2;
        float a11 = r10 * r10 * i0 + r11 * r11 * i1 + r12 * r12 * i2;
        float a12 = r10 * r20 * i0 + r11 * r21 * i1 + r12 * r22 * i2;
        float a22 = r20 * r20 * i0 + r21 * r21 * i1 + r22 * r22 * i2;

        float px = positions[3 * g + 0];
        float py = positions[3 * g + 1];
        float pz = positions[3 * g + 2];
        float bx = a00 * px + a01 * py + a02 * pz;
        float by = a01 * px + a11 * py + a12 * pz;
        float bz = a02 * px + a12 * py + a22 * pz;
        float c  = bx * px + by * py + bz * pz;

        const float K = -0.72134752044448169f;  // -0.5 * log2(e)
        v[0] = K * a00;           // x^2
        v[1] = K * a11;           // y^2
        v[2] = K * a22;           // z^2
        v[3] = 2.0f * K * a01;    // xy
        v[4] = 2.0f * K * a02;    // xz
        v[5] = 2.0f * K * a12;    // yz
        v[6] = -2.0f * K * bx;    // x
        v[7] = -2.0f * K * by;    // y
        v[8] = -2.0f * K * bz;    // z   (scalar tail)
        v[9] = K * c + log2f(fmaxf(intensities[g], 1e-30f));  // const (scalar)
    }

    float* base = g_b + (size_t)(g >> 3) * CHUNK_FLOATS;
    int i = g & 7;
#pragma unroll
    for (int j = 0; j < 4; j++) {
        uint32_t h0, l0, h1, l1;
        tf32split(v[j], h0, l0);
        tf32split(v[j + 4], h1, l1);
        float4 w;
        w.x = __uint_as_float(h0);
        w.y = __uint_as_float(h1);
        w.z = __uint_as_float(l0);
        w.w = __uint_as_float(l1);
        *(float4*)(base + (i * 4 + j) * 4) = w;
    }
    base[128 + i * 2 + 0] = v[8];
    base[128 + i * 2 + 1] = v[9];
}

// ---------------------------------------------------------------------------
// Main: persistent CTAs; ticket = (256-pt block) x (256-gaussian split),
// pt-major: A fragments and accumulators persist across gsplits.
// ---------------------------------------------------------------------------
__global__ void __launch_bounds__(256, CTAS_PER_SM)
gauss_kernel(const float* __restrict__ pts, float* __restrict__ out,
             int M, int pt_blocks, int gsplits, int n_ctas) {
    extern __shared__ __align__(16) float smb[];  // 2 * SPLIT_FLOATS

    const int tid  = threadIdx.x;
    const int wid  = tid >> 5;
    const int lane = tid & 31;
    const int j    = lane & 3;      // threadID_in_group
    const int grp  = lane >> 2;     // groupID (B col / D row / A row)
    const int boff = (grp * 4 + j) * 4;
    const int soff = 128 + j * 4;

    const long long tickets = (long long)pt_blocks * gsplits;
    const int t0 = (int)(((long long)blockIdx.x * tickets) / n_ctas);
    const int t1 = (int)(((long long)(blockIdx.x + 1) * tickets) / n_ctas);
    if (t0 >= t1) return;

    const uint32_t sb0 = smem_u32(smb);
    const uint32_t sb1 = sb0 + SPLIT_FLOATS * 4;

    auto stage = [&](int tk, uint32_t dst) {
        const int gs = tk % gsplits;
        const char* src = (const char*)(g_b + (size_t)gs * SPLIT_FLOATS);
#pragma unroll
        for (int i = tid; i < SPLIT_FLOATS / 4; i += 256)
            cp_async16(dst + (uint32_t)i * 16u, src + (size_t)i * 16);
        cp_commit();
    };

    stage(t0, sb0);

    uint32_t ahi[2][4], alo[2][4];
    float zr[2][2];
    float acc[2][2];
    int cur_pt = -1;
    int pbase = 0;

    for (int tk = t0; tk < t1; ++tk) {
        const int buf = (tk - t0) & 1;

        cp_wait0();
        __syncthreads();              // buffer(tk) staged; all warps past buf reuse
        if (tk + 1 < t1) stage(tk + 1, buf ? sb0 : sb1);

        const int ptb = tk / gsplits;
        if (ptb != cur_pt) {
            // flush accumulators of the previous point block
            if (cur_pt >= 0) {
#pragma unroll
                for (int tI = 0; tI < 2; tI++)
#pragma unroll
                    for (int rI = 0; rI < 2; rI++) {
                        float v = acc[tI][rI];
                        v += __shfl_xor_sync(0xffffffffu, v, 1);
                        v += __shfl_xor_sync(0xffffffffu, v, 2);
                        int p = pbase + tI * 16 + rI * 8;
                        if (j == 0 && p < M) atomicAdd(out + p, v);
                    }
            }
            cur_pt = ptb;
            pbase = ptb * PTB + wid * 32 + grp;
#pragma unroll
            for (int tI = 0; tI < 2; tI++) {
#pragma unroll
                for (int rI = 0; rI < 2; rI++) {
                    int p = pbase + tI * 16 + rI * 8;
                    float x = 0.f, y = 0.f, z = 0.f;
                    if (p < M) { x = pts[3 * p]; y = pts[3 * p + 1]; z = pts[3 * p + 2]; }
                    float m0 = (j == 0) ? x * x : (j == 1) ? y * y
                             : (j == 2) ? z * z : x * y;
                    float m1 = (j == 0) ? x * z : (j == 1) ? y * z
                             : (j == 2) ? x : y;
                    tf32split(m0, ahi[tI][0 + rI], alo[tI][0 + rI]);
                    tf32split(m1, ahi[tI][2 + rI], alo[tI][2 + rI]);
                    zr[tI][rI] = z;
                    acc[tI][rI] = 0.f;
                }
            }
        }

        const float* cb = smb + (buf ? SPLIT_FLOATS : 0);
        // software-pipelined B fragment + scalar tail
        float4 bv = *(const float4*)(cb + boff);
        float4 sc = *(const float4*)(cb + soff);

#pragma unroll 2
        for (int c = 0; c < NCHUNK; ++c) {
            const float* nb = cb + CHUNK_FLOATS;
            float4 bvn = bv, scn = sc;
            if (c + 1 < NCHUNK) {
                bvn = *(const float4*)(nb + boff);
                scn = *(const float4*)(nb + soff);
            }

            const uint32_t bh0 = __float_as_uint(bv.x);
            const uint32_t bh1 = __float_as_uint(bv.y);
            const uint32_t bl0 = __float_as_uint(bv.z);
            const uint32_t bl1 = __float_as_uint(bv.w);

#pragma unroll
            for (int tI = 0; tI < 2; tI++) {
                float d[4];
                float c0 = fmaf(sc.x, zr[tI][0], sc.y);
                float c1 = fmaf(sc.z, zr[tI][0], sc.w);
                float c2 = fmaf(sc.x, zr[tI][1], sc.y);
                float c3 = fmaf(sc.z, zr[tI][1], sc.w);
                mma8(d, ahi[tI], bh0, bh1, c0, c1, c2, c3);          // hi*hi+tail
                mma8(d, ahi[tI], bl0, bl1, d[0], d[1], d[2], d[3]);  // hi*lo
                mma8(d, alo[tI], bh0, bh1, d[0], d[1], d[2], d[3]);  // lo*hi

                // hybrid exp2: move ~1.5 of 8 values per chunk to the FMA pipe
                // (tile0.d[3] every chunk; tile1.d[3] on even chunks).
                bool poly = (tI == 0) || ((c & 1) == 0);
                acc[tI][0] += ex2(d[0]) + ex2(d[1]);
                acc[tI][1] += ex2(d[2]) + (poly ? exp2poly(d[3]) : ex2(d[3]));
            }

            bv = bvn;
            sc = scn;
            cb = nb;
        }
        __syncthreads();   // all warps done reading buf before it is restaged
    }

    // final flush
    if (cur_pt >= 0) {
#pragma unroll
        for (int tI = 0; tI < 2; tI++)
#pragma unroll
            for (int rI = 0; rI < 2; rI++) {
                float v = acc[tI][rI];
                v += __shfl_xor_sync(0xffffffffu, v, 1);
                v += __shfl_xor_sync(0xffffffffu, v, 2);
                int p = pbase + tI * 16 + rI * 8;
                if (j == 0 && p < M) atomicAdd(out + p, v);
            }
    }
}

// ---------------------------------------------------------------------------
extern "C" void kernel_launch(void* const* d_in, const int* in_sizes, int n_in,
                              void* d_out, int out_size) {
    const float* sample_points = (const float*)d_in[0];
    const float* positions     = (const float*)d_in[1];
    const float* scales        = (const float*)d_in[2];
    const float* rotations     = (const float*)d_in[3];
    const float* intensities   = (const float*)d_in[4];
    float* out = (float*)d_out;

    int M = in_sizes[0] / 3;
    int n = in_sizes[4];
    int n_pad = ((n + SPLIT_G - 1) / SPLIT_G) * SPLIT_G;
    if (n_pad > NG_MAX) n_pad = NG_MAX;

    cudaMemsetAsync(out, 0, (size_t)out_size * sizeof(float));

    prep_kernel<<<(n_pad + 127) / 128, 128>>>(positions, scales, rotations,
                                              intensities, n, n_pad);

    int sms = 148;
    cudaDeviceGetAttribute(&sms, cudaDevAttrMultiProcessorCount, 0);

    int pt_blocks = (M + PTB - 1) / PTB;      // 256
    int gsplits   = n_pad / SPLIT_G;          // 16
    long long tickets = (long long)pt_blocks * gsplits;  // 4096

    int n_ctas = sms * CTAS_PER_SM;
    if ((long long)n_ctas > tickets) n_ctas = (int)tickets;

    gauss_kernel<<<n_ctas, 256, 2 * SPLIT_FLOATS * 4>>>(
        sample_points, out, M, pt_blocks, gsplits, n_ctas);
}

// round 15
// speedup vs baseline: 1.1656x; 1.1656x over previous
#include <cuda_runtime.h>
#include <cstdint>

// ---------------------------------------------------------------------------
// out[m] = sum_n I_n * exp(-0.5 (x-mu)^T A (x-mu))
//        = sum_n exp2( monomials(x_m) . coef_n )       (everything folded)
// coef order k=0..7 : x2,y2,z2,xy | xz,yz,x,y   -> handled by mma.sync tf32
// k=8 (z), k=9 (1=cf) -> scalar f32 tail folded into the MMA C operand.
//
// R15: R13 math, occupancy push: __launch_bounds__(256,4) (64-reg cap ->
//      4 CTAs/SM, 8 warps/SMSP) to lift the ~0.5 issue-rate ceiling; B
//      fragment loads unpipelined (extra warps cover LDS latency), unroll 4.
// ---------------------------------------------------------------------------

#define NG_MAX 8192
#define CHUNK_FLOATS 144   // per 8-gaussian chunk: 8*16 mma floats + 16 scalar
#define SPLIT_G 256
#define NCHUNK 32          // chunks per split
#define SPLIT_FLOATS (NCHUNK * CHUNK_FLOATS)   // 4608 floats = 18432 B
#define PTB 256            // points per CTA ticket
#define CTAS_PER_SM 4

__device__ __align__(16) float g_b[(NG_MAX / 8) * CHUNK_FLOATS];

// ---- helpers ---------------------------------------------------------------
__device__ __forceinline__ float ex2(float x) {
    float y;
    asm("ex2.approx.ftz.f32 %0, %1;" : "=f"(y) : "f"(x));
    return y;
}
__device__ __forceinline__ uint32_t tf32_of(float v) {
    uint32_t r;
    asm("cvt.rna.tf32.f32 %0, %1;" : "=r"(r) : "f"(v));
    return r;
}
__device__ __forceinline__ void tf32split(float v, uint32_t& hi, uint32_t& lo) {
    hi = tf32_of(v);
    lo = tf32_of(v - __uint_as_float(hi));
}
__device__ __forceinline__ uint32_t smem_u32(const void* p) {
    uint32_t a;
    asm("{ .reg .u64 t; cvta.to.shared.u64 t, %1; cvt.u32.u64 %0, t; }"
        : "=r"(a) : "l"(p));
    return a;
}
__device__ __forceinline__ void cp_async16(uint32_t dst, const void* src) {
    asm volatile("cp.async.cg.shared.global [%0], [%1], 16;"
                 :: "r"(dst), "l"(src));
}
__device__ __forceinline__ void cp_commit() {
    asm volatile("cp.async.commit_group;");
}
__device__ __forceinline__ void cp_wait0() {
    asm volatile("cp.async.wait_group 0;");
}

// D = A(tf32) * B(tf32) + C   (m16n8k8, row.col)
__device__ __forceinline__ void mma8(float d[4], const uint32_t a[4],
                                     uint32_t b0, uint32_t b1,
                                     float c0, float c1, float c2, float c3) {
    asm("mma.sync.aligned.m16n8k8.row.col.f32.tf32.tf32.f32 "
        "{%0,%1,%2,%3}, {%4,%5,%6,%7}, {%8,%9}, {%10,%11,%12,%13};"
        : "=f"(d[0]), "=f"(d[1]), "=f"(d[2]), "=f"(d[3])
        : "r"(a[0]), "r"(a[1]), "r"(a[2]), "r"(a[3]),
          "r"(b0), "r"(b1),
          "f"(c0), "f"(c1), "f"(c2), "f"(c3));
}

// ---------------------------------------------------------------------------
// Prep: 10 coefficients per gaussian, packed for per-lane fragment loads.
// chunk c = g/8, slot i = g%8, chunk base = c*144 floats:
//   mma region  [(i*4 + j)*4 .. +4) = (hi[v_j], hi[v_{j+4}], lo[v_j], lo[v_{j+4}])
//   scalar      [128 + i*2]         = (v8 (z coef), v9 (cf))
// ---------------------------------------------------------------------------
__global__ void prep_kernel(const float* __restrict__ positions,
                            const float* __restrict__ scales,
                            const float* __restrict__ rotations,
                            const float* __restrict__ intensities,
                            int n, int n_pad) {
    int g = blockIdx.x * blockDim.x + threadIdx.x;
    if (g >= n_pad || g >= NG_MAX) return;

    float v[10];
    if (g >= n) {
#pragma unroll
        for (int k = 0; k < 9; k++) v[k] = 0.0f;
        v[9] = -1000.0f;  // exp2 -> 0
    } else {
        float qw = rotations[4 * g + 0];
        float qx = rotations[4 * g + 1];
        float qy = rotations[4 * g + 2];
        float qz = rotations[4 * g + 3];
        float nrm = sqrtf(qw * qw + qx * qx + qy * qy + qz * qz);
        float inv = 1.0f / (nrm + 1e-8f);
        qw *= inv; qx *= inv; qy *= inv; qz *= inv;

        float r00 = 1.0f - 2.0f * (qy * qy + qz * qz);
        float r01 = 2.0f * (qx * qy - qz * qw);
        float r02 = 2.0f * (qx * qz + qy * qw);
        float r10 = 2.0f * (qx * qy + qz * qw);
        float r11 = 1.0f - 2.0f * (qx * qx + qz * qz);
        float r12 = 2.0f * (qy * qz - qx * qw);
        float r20 = 2.0f * (qx * qz - qy * qw);
        float r21 = 2.0f * (qy * qz + qx * qw);
        float r22 = 1.0f - 2.0f * (qx * qx + qy * qy);

        float s0 = fabsf(scales[3 * g + 0]) + 1e-6f;
        float s1 = fabsf(scales[3 * g + 1]) + 1e-6f;
        float s2 = fabsf(scales[3 * g + 2]) + 1e-6f;
        float i0 = 1.0f / (s0 * s0);
        float i1 = 1.0f / (s1 * s1);
        float i2 = 1.0f / (s2 * s2);

        float a00 = r00 * r00 * i0 + r01 * r01 * i1 + r02 * r02 * i2;
        float a01 = r00 * r10 * i0 + r01 * r11 * i1 + r02 * r12 * i2;
        float a02 = r00 * r20 * i0 + r01 * r21 * i1 + r02 * r22 * i2;
        float a11 = r10 * r10 * i0 + r11 * r11 * i1 + r12 * r12 * i2;
        float a12 = r10 * r20 * i0 + r11 * r21 * i1 + r12 * r22 * i2;
        float a22 = r20 * r20 * i0 + r21 * r21 * i1 + r22 * r22 * i2;

        float px = positions[3 * g + 0];
        float py = positions[3 * g + 1];
        float pz = positions[3 * g + 2];
        float bx = a00 * px + a01 * py + a02 * pz;
        float by = a01 * px + a11 * py + a12 * pz;
        float bz = a02 * px + a12 * py + a22 * pz;
        float c  = bx * px + by * py + bz * pz;

        const float K = -0.72134752044448169f;  // -0.5 * log2(e)
        v[0] = K * a00;           // x^2
        v[1] = K * a11;           // y^2
        v[2] = K * a22;           // z^2
        v[3] = 2.0f * K * a01;    // xy
        v[4] = 2.0f * K * a02;    // xz
        v[5] = 2.0f * K * a12;    // yz
        v[6] = -2.0f * K * bx;    // x
        v[7] = -2.0f * K * by;    // y
        v[8] = -2.0f * K * bz;    // z   (scalar tail)
        v[9] = K * c + log2f(fmaxf(intensities[g], 1e-30f));  // const (scalar)
    }

    float* base = g_b + (size_t)(g >> 3) * CHUNK_FLOATS;
    int i = g & 7;
#pragma unroll
    for (int j = 0; j < 4; j++) {
        uint32_t h0, l0, h1, l1;
        tf32split(v[j], h0, l0);
        tf32split(v[j + 4], h1, l1);
        float4 w;
        w.x = __uint_as_float(h0);
        w.y = __uint_as_float(h1);
        w.z = __uint_as_float(l0);
        w.w = __uint_as_float(l1);
        *(float4*)(base + (i * 4 + j) * 4) = w;
    }
    base[128 + i * 2 + 0] = v[8];
    base[128 + i * 2 + 1] = v[9];
}

// ---------------------------------------------------------------------------
// Main: persistent CTAs; ticket = (256-pt block) x (256-gaussian split),
// pt-major: A fragments and accumulators persist across gsplits.
// ---------------------------------------------------------------------------
__global__ void __launch_bounds__(256, CTAS_PER_SM)
gauss_kernel(const float* __restrict__ pts, float* __restrict__ out,
             int M, int pt_blocks, int gsplits, int n_ctas) {
    extern __shared__ __align__(16) float smb[];  // 2 * SPLIT_FLOATS

    const int tid  = threadIdx.x;
    const int wid  = tid >> 5;
    const int lane = tid & 31;
    const int j    = lane & 3;      // threadID_in_group
    const int grp  = lane >> 2;     // groupID (B col / D row / A row)
    const int boff = (grp * 4 + j) * 4;
    const int soff = 128 + j * 4;

    const long long tickets = (long long)pt_blocks * gsplits;
    const int t0 = (int)(((long long)blockIdx.x * tickets) / n_ctas);
    const int t1 = (int)(((long long)(blockIdx.x + 1) * tickets) / n_ctas);
    if (t0 >= t1) return;

    const uint32_t sb0 = smem_u32(smb);
    const uint32_t sb1 = sb0 + SPLIT_FLOATS * 4;

    auto stage = [&](int tk, uint32_t dst) {
        const int gs = tk % gsplits;
        const char* src = (const char*)(g_b + (size_t)gs * SPLIT_FLOATS);
#pragma unroll
        for (int i = tid; i < SPLIT_FLOATS / 4; i += 256)
            cp_async16(dst + (uint32_t)i * 16u, src + (size_t)i * 16);
        cp_commit();
    };

    stage(t0, sb0);

    uint32_t ahi[2][4], alo[2][4];
    float zr[2][2];
    float acc[2][2];
    int cur_pt = -1;
    int pbase = 0;

    for (int tk = t0; tk < t1; ++tk) {
        const int buf = (tk - t0) & 1;

        cp_wait0();
        __syncthreads();              // buffer(tk) staged; all warps past buf reuse
        if (tk + 1 < t1) stage(tk + 1, buf ? sb0 : sb1);

        const int ptb = tk / gsplits;
        if (ptb != cur_pt) {
            // flush accumulators of the previous point block
            if (cur_pt >= 0) {
#pragma unroll
                for (int tI = 0; tI < 2; tI++)
#pragma unroll
                    for (int rI = 0; rI < 2; rI++) {
                        float v = acc[tI][rI];
                        v += __shfl_xor_sync(0xffffffffu, v, 1);
                        v += __shfl_xor_sync(0xffffffffu, v, 2);
                        int p = pbase + tI * 16 + rI * 8;
                        if (j == 0 && p < M) atomicAdd(out + p, v);
                    }
            }
            cur_pt = ptb;
            pbase = ptb * PTB + wid * 32 + grp;
#pragma unroll
            for (int tI = 0; tI < 2; tI++) {
#pragma unroll
                for (int rI = 0; rI < 2; rI++) {
                    int p = pbase + tI * 16 + rI * 8;
                    float x = 0.f, y = 0.f, z = 0.f;
                    if (p < M) { x = pts[3 * p]; y = pts[3 * p + 1]; z = pts[3 * p + 2]; }
                    float m0 = (j == 0) ? x * x : (j == 1) ? y * y
                             : (j == 2) ? z * z : x * y;
                    float m1 = (j == 0) ? x * z : (j == 1) ? y * z
                             : (j == 2) ? x : y;
                    tf32split(m0, ahi[tI][0 + rI], alo[tI][0 + rI]);
                    tf32split(m1, ahi[tI][2 + rI], alo[tI][2 + rI]);
                    zr[tI][rI] = z;
                    acc[tI][rI] = 0.f;
                }
            }
        }

        const float* cb = smb + (buf ? SPLIT_FLOATS : 0);

#pragma unroll 4
        for (int c = 0; c < NCHUNK; ++c) {
            float4 bv = *(const float4*)(cb + boff);
            float4 sc = *(const float4*)(cb + soff);

            const uint32_t bh0 = __float_as_uint(bv.x);
            const uint32_t bh1 = __float_as_uint(bv.y);
            const uint32_t bl0 = __float_as_uint(bv.z);
            const uint32_t bl1 = __float_as_uint(bv.w);

#pragma unroll
            for (int tI = 0; tI < 2; tI++) {
                float d[4];
                float c0 = fmaf(sc.x, zr[tI][0], sc.y);
                float c1 = fmaf(sc.z, zr[tI][0], sc.w);
                float c2 = fmaf(sc.x, zr[tI][1], sc.y);
                float c3 = fmaf(sc.z, zr[tI][1], sc.w);
                mma8(d, ahi[tI], bh0, bh1, c0, c1, c2, c3);          // hi*hi+tail
                mma8(d, ahi[tI], bl0, bl1, d[0], d[1], d[2], d[3]);  // hi*lo
                mma8(d, alo[tI], bh0, bh1, d[0], d[1], d[2], d[3]);  // lo*hi
                acc[tI][0] += ex2(d[0]) + ex2(d[1]);
                acc[tI][1] += ex2(d[2]) + ex2(d[3]);
            }

            cb += CHUNK_FLOATS;
        }
        __syncthreads();   // all warps done reading buf before it is restaged
    }

    // final flush
    if (cur_pt >= 0) {
#pragma unroll
        for (int tI = 0; tI < 2; tI++)
#pragma unroll
            for (int rI = 0; rI < 2; rI++) {
                float v = acc[tI][rI];
                v += __shfl_xor_sync(0xffffffffu, v, 1);
                v += __shfl_xor_sync(0xffffffffu, v, 2);
                int p = pbase + tI * 16 + rI * 8;
                if (j == 0 && p < M) atomicAdd(out + p, v);
            }
    }
}

// ---------------------------------------------------------------------------
extern "C" void kernel_launch(void* const* d_in, const int* in_sizes, int n_in,
                              void* d_out, int out_size) {
    const float* sample_points = (const float*)d_in[0];
    const float* positions     = (const float*)d_in[1];
    const float* scales        = (const float*)d_in[2];
    const float* rotations     = (const float*)d_in[3];
    const float* intensities   = (const float*)d_in[4];
    float* out = (float*)d_out;

    int M = in_sizes[0] / 3;
    int n = in_sizes[4];
    int n_pad = ((n + SPLIT_G - 1) / SPLIT_G) * SPLIT_G;
    if (n_pad > NG_MAX) n_pad = NG_MAX;

    cudaMemsetAsync(out, 0, (size_t)out_size * sizeof(float));

    prep_kernel<<<(n_pad + 127) / 128, 128>>>(positions, scales, rotations,
                                              intensities, n, n_pad);

    int sms = 148;
    cudaDeviceGetAttribute(&sms, cudaDevAttrMultiProcessorCount, 0);

    int pt_blocks = (M + PTB - 1) / PTB;      // 256
    int gsplits   = n_pad / SPLIT_G;          // 16
    long long tickets = (long long)pt_blocks * gsplits;  // 4096

    int n_ctas = sms * CTAS_PER_SM;
    if ((long long)n_ctas > tickets) n_ctas = (int)tickets;

    gauss_kernel<<<n_ctas, 256, 2 * SPLIT_FLOATS * 4>>>(
        sample_points, out, M, pt_blocks, gsplits, n_ctas);
}

// round 16
// speedup vs baseline: 1.3621x; 1.1685x over previous
#include <cuda_runtime.h>
#include <cuda_fp16.h>
#include <cstdint>

// ---------------------------------------------------------------------------
// out[m] = sum_n I_n * exp(-0.5 (x-mu)^T A (x-mu))
//        = sum_n exp2( monomials(x_m) . coef_n )       (everything folded)
// coef order k=0..7 : x2,y2 | z2,xy | xz,yz | x,y  -> handled by mma.sync f16
// k=8 (z), k=9 (1=cf) -> scalar f32 tail folded into the MMA C operand.
//
// R16: 2x f16.m16n8k16 MMA replaces 3x tf32.m16n8k8 (same 3-term hi/lo split,
//      f16 mantissa == tf32 mantissa): A=[hi|lo]; MMA1 B=[Bhi|Bhi] gives
//      hi*Bhi+lo*Bhi; MMA2 B=[Blo|0] gives hi*Blo. Tensor work -33%, B LDS
//      halves, smem halves. Epilogue/scheduling identical to R15.
// ---------------------------------------------------------------------------

#define NG_MAX 8192
#define CHUNK_FLOATS 80    // per 8-gaussian chunk: 8*4 uint2 b-frags + 16 scalar
#define SPLIT_G 256
#define NCHUNK 32          // chunks per split
#define SPLIT_FLOATS (NCHUNK * CHUNK_FLOATS)   // 2560 floats = 10240 B
#define PTB 256            // points per CTA ticket
#define CTAS_PER_SM 4

__device__ __align__(16) float g_b[(NG_MAX / 8) * CHUNK_FLOATS];

// ---- helpers ---------------------------------------------------------------
__device__ __forceinline__ float ex2(float x) {
    float y;
    asm("ex2.approx.ftz.f32 %0, %1;" : "=f"(y) : "f"(x));
    return y;
}
// pack two f32 -> f16x2 (v0 in LOW half)
__device__ __forceinline__ uint32_t pkh2(float v0, float v1) {
    uint32_t r;
    asm("cvt.rn.f16x2.f32 %0, %1, %2;" : "=r"(r) : "f"(v1), "f"(v0));
    return r;
}
__device__ __forceinline__ float h2f_lo(uint32_t h2) {
    float f;
    asm("{ .reg .f16 a, b;\n\t mov.b32 {a, b}, %1;\n\t cvt.f32.f16 %0, a; }"
        : "=f"(f) : "r"(h2));
    return f;
}
__device__ __forceinline__ float h2f_hi(uint32_t h2) {
    float f;
    asm("{ .reg .f16 a, b;\n\t mov.b32 {a, b}, %1;\n\t cvt.f32.f16 %0, b; }"
        : "=f"(f) : "r"(h2));
    return f;
}
// hi/lo f16 split of a pair of f32 values -> two f16x2 regs
__device__ __forceinline__ void h2split(float m0, float m1,
                                        uint32_t& hi2, uint32_t& lo2) {
    hi2 = pkh2(m0, m1);
    lo2 = pkh2(m0 - h2f_lo(hi2), m1 - h2f_hi(hi2));
}
__device__ __forceinline__ uint32_t smem_u32(const void* p) {
    uint32_t a;
    asm("{ .reg .u64 t; cvta.to.shared.u64 t, %1; cvt.u32.u64 %0, t; }"
        : "=r"(a) : "l"(p));
    return a;
}
__device__ __forceinline__ void cp_async16(uint32_t dst, const void* src) {
    asm volatile("cp.async.cg.shared.global [%0], [%1], 16;"
                 :: "r"(dst), "l"(src));
}
__device__ __forceinline__ void cp_commit() {
    asm volatile("cp.async.commit_group;");
}
__device__ __forceinline__ void cp_wait0() {
    asm volatile("cp.async.wait_group 0;");
}

// D = A(f16) * B(f16) + C   (m16n8k16, row.col, f32 accumulate)
__device__ __forceinline__ void mma16(float d[4],
                                      uint32_t a0, uint32_t a1,
                                      uint32_t a2, uint32_t a3,
                                      uint32_t b0, uint32_t b1,
                                      float c0, float c1, float c2, float c3) {
    asm("mma.sync.aligned.m16n8k16.row.col.f32.f16.f16.f32 "
        "{%0,%1,%2,%3}, {%4,%5,%6,%7}, {%8,%9}, {%10,%11,%12,%13};"
        : "=f"(d[0]), "=f"(d[1]), "=f"(d[2]), "=f"(d[3])
        : "r"(a0), "r"(a1), "r"(a2), "r"(a3),
          "r"(b0), "r"(b1),
          "f"(c0), "f"(c1), "f"(c2), "f"(c3));
}

// ---------------------------------------------------------------------------
// Prep: 10 coefficients per gaussian; B-fragments pre-packed as f16 hi/lo.
// chunk c = g/8, slot i = g%8, chunk base = c*80 floats:
//   b-frag uint2 at [(i*4 + j)*2 floats]: x = f16x2(hi[2j], hi[2j+1]),
//                                          y = f16x2(lo[2j], lo[2j+1])
//   scalar  [64 + i*2] = (v8 (z coef), v9 (cf))
// ---------------------------------------------------------------------------
__global__ void prep_kernel(const float* __restrict__ positions,
                            const float* __restrict__ scales,
                            const float* __restrict__ rotations,
                            const float* __restrict__ intensities,
                            int n, int n_pad) {
    int g = blockIdx.x * blockDim.x + threadIdx.x;
    if (g >= n_pad || g >= NG_MAX) return;

    float v[10];
    if (g >= n) {
#pragma unroll
        for (int k = 0; k < 9; k++) v[k] = 0.0f;
        v[9] = -1000.0f;  // exp2 -> 0
    } else {
        float qw = rotations[4 * g + 0];
        float qx = rotations[4 * g + 1];
        float qy = rotations[4 * g + 2];
        float qz = rotations[4 * g + 3];
        float nrm = sqrtf(qw * qw + qx * qx + qy * qy + qz * qz);
        float inv = 1.0f / (nrm + 1e-8f);
        qw *= inv; qx *= inv; qy *= inv; qz *= inv;

        float r00 = 1.0f - 2.0f * (qy * qy + qz * qz);
        float r01 = 2.0f * (qx * qy - qz * qw);
        float r02 = 2.0f * (qx * qz + qy * qw);
        float r10 = 2.0f * (qx * qy + qz * qw);
        float r11 = 1.0f - 2.0f * (qx * qx + qz * qz);
        float r12 = 2.0f * (qy * qz - qx * qw);
        float r20 = 2.0f * (qx * qz - qy * qw);
        float r21 = 2.0f * (qy * qz + qx * qw);
        float r22 = 1.0f - 2.0f * (qx * qx + qy * qy);

        float s0 = fabsf(scales[3 * g + 0]) + 1e-6f;
        float s1 = fabsf(scales[3 * g + 1]) + 1e-6f;
        float s2 = fabsf(scales[3 * g + 2]) + 1e-6f;
        float i0 = 1.0f / (s0 * s0);
        float i1 = 1.0f / (s1 * s1);
        float i2 = 1.0f / (s2 * s2);

        float a00 = r00 * r00 * i0 + r01 * r01 * i1 + r02 * r02 * i2;
        float a01 = r00 * r10 * i0 + r01 * r11 * i1 + r02 * r12 * i2;
        float a02 = r00 * r20 * i0 + r01 * r21 * i1 + r02 * r22 * i2;
        float a11 = r10 * r10 * i0 + r11 * r11 * i1 + r12 * r12 * i2;
        float a12 = r10 * r20 * i0 + r11 * r21 * i1 + r12 * r22 * i2;
        float a22 = r20 * r20 * i0 + r21 * r21 * i1 + r22 * r22 * i2;

        float px = positions[3 * g + 0];
        float py = positions[3 * g + 1];
        float pz = positions[3 * g + 2];
        float bx = a00 * px + a01 * py + a02 * pz;
        float by = a01 * px + a11 * py + a12 * pz;
        float bz = a02 * px + a12 * py + a22 * pz;
        float c  = bx * px + by * py + bz * pz;

        const float K = -0.72134752044448169f;  // -0.5 * log2(e)
        v[0] = K * a00;           // x^2
        v[1] = K * a11;           // y^2
        v[2] = K * a22;           // z^2
        v[3] = 2.0f * K * a01;    // xy
        v[4] = 2.0f * K * a02;    // xz
        v[5] = 2.0f * K * a12;    // yz
        v[6] = -2.0f * K * bx;    // x
        v[7] = -2.0f * K * by;    // y
        v[8] = -2.0f * K * bz;    // z   (scalar tail)
        v[9] = K * c + log2f(fmaxf(intensities[g], 1e-30f));  // const (scalar)
    }

    float* base = g_b + (size_t)(g >> 3) * CHUNK_FLOATS;
    int i = g & 7;
#pragma unroll
    for (int j = 0; j < 4; j++) {
        uint32_t hi2, lo2;
        h2split(v[2 * j], v[2 * j + 1], hi2, lo2);
        ((uint2*)base)[i * 4 + j] = make_uint2(hi2, lo2);
    }
    base[64 + i * 2 + 0] = v[8];
    base[64 + i * 2 + 1] = v[9];
}

// ---------------------------------------------------------------------------
// Main: persistent CTAs; ticket = (256-pt block) x (256-gaussian split),
// pt-major: A fragments and accumulators persist across gsplits.
// ---------------------------------------------------------------------------
__global__ void __launch_bounds__(256, CTAS_PER_SM)
gauss_kernel(const float* __restrict__ pts, float* __restrict__ out,
             int M, int pt_blocks, int gsplits, int n_ctas) {
    extern __shared__ __align__(16) float smb[];  // 2 * SPLIT_FLOATS

    const int tid  = threadIdx.x;
    const int wid  = tid >> 5;
    const int lane = tid & 31;
    const int j    = lane & 3;      // threadID_in_group (k-pair selector)
    const int grp  = lane >> 2;     // groupID (B col / D row / A row)
    const int boffB = (grp * 4 + j) * 8;   // byte offset of uint2 b-frag
    const int soff  = 64 + j * 4;          // float offset of scalar tail

    const long long tickets = (long long)pt_blocks * gsplits;
    const int t0 = (int)(((long long)blockIdx.x * tickets) / n_ctas);
    const int t1 = (int)(((long long)(blockIdx.x + 1) * tickets) / n_ctas);
    if (t0 >= t1) return;

    const uint32_t sb0 = smem_u32(smb);
    const uint32_t sb1 = sb0 + SPLIT_FLOATS * 4;

    auto stage = [&](int tk, uint32_t dst) {
        const int gs = tk % gsplits;
        const char* src = (const char*)(g_b + (size_t)gs * SPLIT_FLOATS);
#pragma unroll
        for (int i = tid; i < SPLIT_FLOATS / 4; i += 256)
            cp_async16(dst + (uint32_t)i * 16u, src + (size_t)i * 16);
        cp_commit();
    };

    stage(t0, sb0);

    // A fragments: aH/aL[tile][row-half], f16x2 (monomials 2j, 2j+1)
    uint32_t aH[2][2], aL[2][2];
    float zr[2][2];
    float acc[2][2];
    int cur_pt = -1;
    int pbase = 0;

    for (int tk = t0; tk < t1; ++tk) {
        const int buf = (tk - t0) & 1;

        cp_wait0();
        __syncthreads();              // buffer(tk) staged; all warps past buf reuse
        if (tk + 1 < t1) stage(tk + 1, buf ? sb0 : sb1);

        const int ptb = tk / gsplits;
        if (ptb != cur_pt) {
            // flush accumulators of the previous point block
            if (cur_pt >= 0) {
#pragma unroll
                for (int tI = 0; tI < 2; tI++)
#pragma unroll
                    for (int rI = 0; rI < 2; rI++) {
                        float v = acc[tI][rI];
                        v += __shfl_xor_sync(0xffffffffu, v, 1);
                        v += __shfl_xor_sync(0xffffffffu, v, 2);
                        int p = pbase + tI * 16 + rI * 8;
                        if (j == 0 && p < M) atomicAdd(out + p, v);
                    }
            }
            cur_pt = ptb;
            pbase = ptb * PTB + wid * 32 + grp;
#pragma unroll
            for (int tI = 0; tI < 2; tI++) {
#pragma unroll
                for (int rI = 0; rI < 2; rI++) {
                    int p = pbase + tI * 16 + rI * 8;
                    float x = 0.f, y = 0.f, z = 0.f;
                    if (p < M) { x = pts[3 * p]; y = pts[3 * p + 1]; z = pts[3 * p + 2]; }
                    // monomial pair (2j, 2j+1) for this point
                    float m0 = (j == 0) ? x * x : (j == 1) ? z * z
                             : (j == 2) ? x * z : x;
                    float m1 = (j == 0) ? y * y : (j == 1) ? x * y
                             : (j == 2) ? y * z : y;
                    h2split(m0, m1, aH[tI][rI], aL[tI][rI]);
                    zr[tI][rI] = z;
                    acc[tI][rI] = 0.f;
                }
            }
        }

        const float* cb = smb + (buf ? SPLIT_FLOATS : 0);

#pragma unroll 4
        for (int c = 0; c < NCHUNK; ++c) {
            uint2  bb = *(const uint2*)((const char*)cb + boffB);
            float4 sc = *(const float4*)(cb + soff);

#pragma unroll
            for (int tI = 0; tI < 2; tI++) {
                float d[4];
                float c0 = fmaf(sc.x, zr[tI][0], sc.y);
                float c1 = fmaf(sc.z, zr[tI][0], sc.w);
                float c2 = fmaf(sc.x, zr[tI][1], sc.y);
                float c3 = fmaf(sc.z, zr[tI][1], sc.w);
                // MMA1: A=[hi|lo], B=[Bhi|Bhi] -> hi*Bhi + lo*Bhi (+ tail)
                mma16(d, aH[tI][0], aH[tI][1], aL[tI][0], aL[tI][1],
                      bb.x, bb.x, c0, c1, c2, c3);
                // MMA2: A=[hi|lo], B=[Blo|0]  -> + hi*Blo
                mma16(d, aH[tI][0], aH[tI][1], aL[tI][0], aL[tI][1],
                      bb.y, 0u, d[0], d[1], d[2], d[3]);
                acc[tI][0] += ex2(d[0]) + ex2(d[1]);
                acc[tI][1] += ex2(d[2]) + ex2(d[3]);
            }

            cb += CHUNK_FLOATS;
        }
        __syncthreads();   // all warps done reading buf before it is restaged
    }

    // final flush
    if (cur_pt >= 0) {
#pragma unroll
        for (int tI = 0; tI < 2; tI++)
#pragma unroll
            for (int rI = 0; rI < 2; rI++) {
                float v = acc[tI][rI];
                v += __shfl_xor_sync(0xffffffffu, v, 1);
                v += __shfl_xor_sync(0xffffffffu, v, 2);
                int p = pbase + tI * 16 + rI * 8;
                if (j == 0 && p < M) atomicAdd(out + p, v);
            }
    }
}

// ---------------------------------------------------------------------------
extern "C" void kernel_launch(void* const* d_in, const int* in_sizes, int n_in,
                              void* d_out, int out_size) {
    const float* sample_points = (const float*)d_in[0];
    const float* positions     = (const float*)d_in[1];
    const float* scales        = (const float*)d_in[2];
    const float* rotations     = (const float*)d_in[3];
    const float* intensities   = (const float*)d_in[4];
    float* out = (float*)d_out;

    int M = in_sizes[0] / 3;
    int n = in_sizes[4];
    int n_pad = ((n + SPLIT_G - 1) / SPLIT_G) * SPLIT_G;
    if (n_pad > NG_MAX) n_pad = NG_MAX;

    cudaMemsetAsync(out, 0, (size_t)out_size * sizeof(float));

    prep_kernel<<<(n_pad + 127) / 128, 128>>>(positions, scales, rotations,
                                              intensities, n, n_pad);

    int sms = 148;
    cudaDeviceGetAttribute(&sms, cudaDevAttrMultiProcessorCount, 0);

    int pt_blocks = (M + PTB - 1) / PTB;      // 256
    int gsplits   = n_pad / SPLIT_G;          // 16
    long long tickets = (long long)pt_blocks * gsplits;  // 4096

    int n_ctas = sms * CTAS_PER_SM;
    if ((long long)n_ctas > tickets) n_ctas = (int)tickets;

    gauss_kernel<<<n_ctas, 256, 2 * SPLIT_FLOATS * 4>>>(
        sample_points, out, M, pt_blocks, gsplits, n_ctas);
}